// round 14
// baseline (speedup 1.0000x reference)
#include <cuda_runtime.h>
#include <cuda_fp16.h>
#include <math.h>
#include <stdint.h>

#define BB 64
#define TT 4096
#define CC 256
#define HH 4
#define HD 64
#define LN_EPS 1e-5f
#define NSPLIT 16
#define TS (TT / NSPLIT)   // 256 t-rows per split

// W image: per head 64 rows x 264 (padded) fp16 = 33792 B = 2112 uint4
#define WPAD 264
#define W_U4_PER_H 2112

// smem layout for k_scores_mma (bytes) — M=128 tile
#define SMEM_X 0
#define SMEM_W (128 * WPAD * 2)                 // 67584
#define SMEM_SC_TOTAL (SMEM_W + 64 * WPAD * 2)  // 101376

// ---------------------------------------------------------------------------
// scratch globals (no allocations allowed)
// ---------------------------------------------------------------------------
__device__ float  g_scores[BB * HH * TT];        // 4 MB (reused as raw-out later)
__device__ float  g_ctx[BB * NSPLIT * HH * CC];  // 16 MB
__device__ float  g_multi[BB * HH * CC];         // 256 KB
__device__ __half g_xh[(size_t)BB * TT * CC];    // 128 MB fp16 mirror of x
__device__ uint4  g_wimg[HH * W_U4_PER_H];       // fp16 W1^T images, padded rows

__device__ __forceinline__ uint32_t smem_to_u32(const void* p) {
    uint32_t a;
    asm("{ .reg .u64 t; cvta.to.shared.u64 t, %1; cvt.u32.u64 %0, t; }" : "=r"(a) : "l"(p));
    return a;
}
__device__ __forceinline__ float tanh_fast(float x) {
    float y;
    asm("tanh.approx.f32 %0, %1;" : "=f"(y) : "f"(x));
    return y;
}

#define LDMATRIX_X4(r0, r1, r2, r3, addr) \
    asm volatile("ldmatrix.sync.aligned.m8n8.x4.shared.b16 {%0,%1,%2,%3}, [%4];" \
                 : "=r"(r0), "=r"(r1), "=r"(r2), "=r"(r3) : "r"(addr))

#define MMA_16816(c, a0, a1, a2, a3, b0, b1) \
    asm volatile("mma.sync.aligned.m16n8k16.row.col.f32.f16.f16.f32 " \
                 "{%0,%1,%2,%3}, {%4,%5,%6,%7}, {%8,%9}, {%0,%1,%2,%3};" \
                 : "+f"((c)[0]), "+f"((c)[1]), "+f"((c)[2]), "+f"((c)[3]) \
                 : "r"(a0), "r"(a1), "r"(a2), "r"(a3), "r"(b0), "r"(b1))

// ---------------------------------------------------------------------------
// Prep: W1[h] (C x HD, d contiguous) -> fp16 (d-row, c-col) padded image
// ---------------------------------------------------------------------------
__global__ void k_prepw(const float* __restrict__ W1) {
    const int h = blockIdx.x;
    __half* img = (__half*)g_wimg + (size_t)h * (64 * WPAD);
    for (int i = threadIdx.x; i < CC * HD; i += blockDim.x) {
        int c = i >> 6, d = i & 63;
        img[d * WPAD + c] = __float2half_rn(W1[(size_t)h * CC * HD + i]);
    }
}

// ---------------------------------------------------------------------------
// Stage 1 (mma.sync fp16): scores[b][h][t] = w2[h].tanh(x[b][t]@W1[h]+b1[h])
// CTA = 128 t-rows x 1 batch; 8 warps. Also streams the fp16-converted x
// tile back to g_xh for the (now half-traffic) context kernel.
// ---------------------------------------------------------------------------
__global__ __launch_bounds__(256, 2) void k_scores_mma(
    const float* __restrict__ x, const float* __restrict__ b1,
    const float* __restrict__ w2)
{
    extern __shared__ char smem[];
    const int tid = threadIdx.x;
    const int wid = tid >> 5;
    const int lid = tid & 31;
    const int t0 = blockIdx.x * 128;
    const int b  = blockIdx.y;
    const uint32_t sbase = smem_to_u32(smem);

    // ---- load X tile (128x256 f32), convert to fp16, smem + g_xh mirror ----
    {
        const float4* xg = (const float4*)(x + ((size_t)b * TT + t0) * CC);
        uint2* xh = (uint2*)(g_xh + ((size_t)b * TT + t0) * CC);
        #pragma unroll
        for (int i = 0; i < 32; i++) {
            int idx = tid + i * 256;
            int m = idx >> 6, c4 = idx & 63;
            float4 v = xg[idx];
            __half2 h0 = __floats2half2_rn(v.x, v.y);
            __half2 h1 = __floats2half2_rn(v.z, v.w);
            uint2 p;
            p.x = *(const uint32_t*)&h0;
            p.y = *(const uint32_t*)&h1;
            *(uint2*)(smem + SMEM_X + m * (WPAD * 2) + c4 * 8) = p;
            xh[idx] = p;                       // coalesced fp16 mirror
        }
    }
    // ---- copy W(0) ----
    {
        uint4* dst = (uint4*)(smem + SMEM_W);
        #pragma unroll
        for (int i = 0; i < 9; i++) {
            int j = tid + i * 256;
            if (j < W_U4_PER_H) dst[j] = g_wimg[j];
        }
    }
    __syncthreads();    // X + W0 visible

    // ---- per-lane ldmatrix base addresses ----
    const int lq = lid >> 3;      // quad 0..3
    const int lr = lid & 7;
    const uint32_t a_base = sbase + SMEM_X +
        ((uint32_t)(wid * 16 + lr + ((lq & 1) << 3)) * (WPAD * 2)) + (((lq >> 1) << 3) << 1);
    uint32_t b_base[4];
    #pragma unroll
    for (int g = 0; g < 4; g++)
        b_base[g] = sbase + SMEM_W +
            ((uint32_t)((g * 2 + (lq >> 1)) * 8 + lr) * (WPAD * 2)) + (((lq & 1) << 3) << 1);

    const int d0 = (lid & 3) * 2;

    #pragma unroll 1
    for (int h = 0; h < HH; h++) {
        float c[8][4];
        #pragma unroll
        for (int nt = 0; nt < 8; nt++)
            #pragma unroll
            for (int j = 0; j < 4; j++) c[nt][j] = 0.f;

        #pragma unroll 4
        for (int ks = 0; ks < 16; ks++) {
            uint32_t a0, a1, a2, a3;
            LDMATRIX_X4(a0, a1, a2, a3, a_base + ks * 32);
            uint32_t br[16];
            #pragma unroll
            for (int g = 0; g < 4; g++)
                LDMATRIX_X4(br[g * 4], br[g * 4 + 1], br[g * 4 + 2], br[g * 4 + 3],
                            b_base[g] + ks * 32);
            #pragma unroll
            for (int nt = 0; nt < 8; nt++) {
                int bi = (nt >> 1) * 4 + (nt & 1) * 2;
                MMA_16816(c[nt], a0, a1, a2, a3, br[bi], br[bi + 1]);
            }
        }

        if (h < HH - 1) {
            __syncthreads();   // all warps done reading W(h)
            // ---- issue W(h+1) copy; overlaps the epilogue below ----
            {
                const uint4* src = g_wimg + (h + 1) * W_U4_PER_H;
                uint4* dst = (uint4*)(smem + SMEM_W);
                #pragma unroll
                for (int i = 0; i < 9; i++) {
                    int j = tid + i * 256;
                    if (j < W_U4_PER_H) dst[j] = src[j];
                }
            }
        }

        // ---- epilogue: + b1, HW tanh, dot w2, reduce over lane quads ----
        float s0 = 0.f, s1 = 0.f;
        #pragma unroll
        for (int nt = 0; nt < 8; nt++) {
            #pragma unroll
            for (int j = 0; j < 2; j++) {
                int d = nt * 8 + d0 + j;
                float bb = __ldg(&b1[h * HD + d]);
                float ww = __ldg(&w2[h * HD + d]);
                s0 += tanh_fast(c[nt][j] + bb) * ww;       // row = groupID
                s1 += tanh_fast(c[nt][2 + j] + bb) * ww;   // row = groupID + 8
            }
        }
        s0 += __shfl_xor_sync(0xffffffffu, s0, 1);
        s0 += __shfl_xor_sync(0xffffffffu, s0, 2);
        s1 += __shfl_xor_sync(0xffffffffu, s1, 1);
        s1 += __shfl_xor_sync(0xffffffffu, s1, 2);
        if ((lid & 3) == 0) {
            int r = wid * 16 + (lid >> 2);
            float* sc = g_scores + ((size_t)(b * HH + h)) * TT + t0;
            sc[r]     = s0;
            sc[r + 8] = s1;
        }

        if (h < HH - 1) __syncthreads();   // W(h+1) ready for next kloop
    }
}

// ---------------------------------------------------------------------------
// Stage 2: softmax over T per (b,h); writes weights into d_out region.
// ---------------------------------------------------------------------------
__global__ __launch_bounds__(256, 1) void k_softmax(float* __restrict__ wout)
{
    const int bh  = blockIdx.x;
    const int tid = threadIdx.x;
    const float* s = g_scores + (size_t)bh * TT;
    float*       w = wout     + (size_t)bh * TT;
    __shared__ float red[256];

    float loc[16];
    float m = -1e30f;
    #pragma unroll
    for (int i = 0; i < 16; i++) { loc[i] = s[tid + i * 256]; m = fmaxf(m, loc[i]); }
    red[tid] = m; __syncthreads();
    for (int st = 128; st > 0; st >>= 1) {
        if (tid < st) red[tid] = fmaxf(red[tid], red[tid + st]);
        __syncthreads();
    }
    m = red[0]; __syncthreads();

    float sum = 0.f;
    #pragma unroll
    for (int i = 0; i < 16; i++) { loc[i] = __expf(loc[i] - m); sum += loc[i]; }
    red[tid] = sum; __syncthreads();
    for (int st = 128; st > 0; st >>= 1) {
        if (tid < st) red[tid] += red[tid + st];
        __syncthreads();
    }
    const float inv = 1.f / red[0];
    #pragma unroll
    for (int i = 0; i < 16; i++) w[tid + i * 256] = loc[i] * inv;
}

// ---------------------------------------------------------------------------
// Stage 3: partial contexts from the fp16 x mirror (half the DRAM traffic).
// 256 threads = 8 t-groups x 32 lanes; each lane owns 8 channels (one uint4).
// ---------------------------------------------------------------------------
__global__ __launch_bounds__(256, 2) void k_ctx(const float* __restrict__ wts)
{
    const int split = blockIdx.x;
    const int b     = blockIdx.y;
    const int tid   = threadIdx.x;
    const int grp   = tid >> 5;     // 0..7
    const int ch    = tid & 31;     // uint4-column (8 halves each)
    __shared__ float ws[HH][TS];            // 4 KB
    __shared__ float red[8][HH][CC];        // 32 KB

    const int tbase = split * TS;
    for (int i = tid; i < HH * TS; i += 256) {
        int hh = i >> 8, tt = i & (TS - 1);
        ws[hh][tt] = wts[((size_t)(b * HH + hh)) * TT + tbase + tt];
    }
    __syncthreads();

    float acc[HH][8] = {};
    const uint4* xp = (const uint4*)(g_xh + ((size_t)b * TT + tbase) * CC) + ch;
    #pragma unroll 4
    for (int tt = grp; tt < TS; tt += 8) {
        uint4 v = xp[(size_t)tt * 32];
        float xf[8];
        {
            float2 f0 = __half22float2(*(__half2*)&v.x);
            float2 f1 = __half22float2(*(__half2*)&v.y);
            float2 f2 = __half22float2(*(__half2*)&v.z);
            float2 f3 = __half22float2(*(__half2*)&v.w);
            xf[0] = f0.x; xf[1] = f0.y; xf[2] = f1.x; xf[3] = f1.y;
            xf[4] = f2.x; xf[5] = f2.y; xf[6] = f3.x; xf[7] = f3.y;
        }
        #pragma unroll
        for (int h = 0; h < HH; h++) {
            float w = ws[h][tt];
            #pragma unroll
            for (int j = 0; j < 8; j++) acc[h][j] += w * xf[j];
        }
    }
    #pragma unroll
    for (int h = 0; h < HH; h++) {
        *(float4*)&red[grp][h][ch * 8]     = *(float4*)&acc[h][0];
        *(float4*)&red[grp][h][ch * 8 + 4] = *(float4*)&acc[h][4];
    }
    __syncthreads();

    for (int n = tid; n < HH * CC; n += 256) {
        int h = n >> 8, c = n & 255;
        float s = 0.f;
        #pragma unroll
        for (int g = 0; g < 8; g++) s += red[g][h][c];
        g_ctx[(((size_t)(b * NSPLIT + split)) * HH + h) * CC + c] = s;
    }
}

// ---------------------------------------------------------------------------
// Stage 4a: reduce splits -> g_multi[b][h*C+c]. grid = B.
// ---------------------------------------------------------------------------
__global__ __launch_bounds__(256, 1) void k_redctx()
{
    const int b   = blockIdx.x;
    const int tid = threadIdx.x;
    #pragma unroll
    for (int rep = 0; rep < 4; rep++) {
        int n = tid + rep * 256;
        float s = 0.f;
        #pragma unroll
        for (int sp = 0; sp < NSPLIT; sp++)
            s += g_ctx[((size_t)(b * NSPLIT + sp)) * (HH * CC) + n];
        g_multi[(size_t)b * (HH * CC) + n] = s;
    }
}

// ---------------------------------------------------------------------------
// Stage 4b: projection, 8 batches per CTA. grid (8 col-tiles, 8 b-groups).
// Raw out -> g_scores scratch (safe: softmax already consumed scores).
// ---------------------------------------------------------------------------
__global__ __launch_bounds__(256, 1) void k_proj(
    const float* __restrict__ Wo, const float* __restrict__ bo)
{
    const int ct  = blockIdx.x;   // 0..7 (32 cols each)
    const int bg  = blockIdx.y;   // 0..7 (8 batches each)
    const int tid = threadIdx.x;
    __shared__ float multi[8][HH * CC];     // 32 KB

    for (int i = tid; i < 8 * HH * CC; i += 256) {
        int bb = i >> 10, n = i & 1023;
        multi[bb][n] = g_multi[(size_t)(bg * 8 + bb) * (HH * CC) + n];
    }
    __syncthreads();

    const int col   = ct * 32 + (tid >> 3);
    const int lane8 = tid & 7;
    const float* wr = Wo + (size_t)col * (HH * CC);
    float v[8] = {};
    #pragma unroll 4
    for (int k = lane8 * 4; k < HH * CC; k += 32) {
        float4 w4 = *(const float4*)&wr[k];
        #pragma unroll
        for (int bb = 0; bb < 8; bb++) {
            v[bb] += w4.x * multi[bb][k]     + w4.y * multi[bb][k + 1]
                   + w4.z * multi[bb][k + 2] + w4.w * multi[bb][k + 3];
        }
    }
    #pragma unroll
    for (int bb = 0; bb < 8; bb++) {
        v[bb] += __shfl_down_sync(0xffffffffu, v[bb], 4, 8);
        v[bb] += __shfl_down_sync(0xffffffffu, v[bb], 2, 8);
        v[bb] += __shfl_down_sync(0xffffffffu, v[bb], 1, 8);
    }
    if (lane8 == 0) {
        const float bv = bo[col];
        #pragma unroll
        for (int bb = 0; bb < 8; bb++)
            g_scores[(size_t)(bg * 8 + bb) * CC + col] = v[bb] + bv;
    }
}

// ---------------------------------------------------------------------------
// Stage 4c: LayerNorm. grid = B.
// ---------------------------------------------------------------------------
__global__ __launch_bounds__(256, 1) void k_ln(
    const float* __restrict__ gamma, const float* __restrict__ beta,
    float* __restrict__ out)
{
    const int b   = blockIdx.x;
    const int tid = threadIdx.x;
    __shared__ float red[256];
    const float v = g_scores[(size_t)b * CC + tid];

    red[tid] = v; __syncthreads();
    for (int st = 128; st > 0; st >>= 1) {
        if (tid < st) red[tid] += red[tid + st];
        __syncthreads();
    }
    const float mu = red[0] * (1.f / CC); __syncthreads();
    const float d = v - mu;
    red[tid] = d * d; __syncthreads();
    for (int st = 128; st > 0; st >>= 1) {
        if (tid < st) red[tid] += red[tid + st];
        __syncthreads();
    }
    const float var = red[0] * (1.f / CC);
    out[(size_t)b * CC + tid] = d * rsqrtf(var + LN_EPS) * gamma[tid] + beta[tid];
}

// ---------------------------------------------------------------------------
extern "C" void kernel_launch(void* const* d_in, const int* in_sizes, int n_in,
                              void* d_out, int out_size)
{
    const float* x     = (const float*)d_in[0];
    const float* W1    = (const float*)d_in[1];
    const float* b1    = (const float*)d_in[2];
    const float* w2    = (const float*)d_in[3];
    const float* Wo    = (const float*)d_in[4];
    const float* bo    = (const float*)d_in[5];
    const float* gamma = (const float*)d_in[6];
    const float* beta  = (const float*)d_in[7];

    float* out = (float*)d_out;           // (B, C)
    float* wts = out + BB * CC;           // (B, H, T)

    cudaFuncSetAttribute(k_scores_mma, cudaFuncAttributeMaxDynamicSharedMemorySize,
                         SMEM_SC_TOTAL);

    k_prepw     <<<HH, 256>>>(W1);
    k_scores_mma<<<dim3(TT / 128, BB), 256, SMEM_SC_TOTAL>>>(x, b1, w2);
    k_softmax   <<<BB * HH, 256>>>(wts);
    k_ctx       <<<dim3(NSPLIT, BB), 256>>>(wts);
    k_redctx    <<<BB, 256>>>();
    k_proj      <<<dim3(8, 8), 256>>>(Wo, bo);
    k_ln        <<<BB, 256>>>(gamma, beta, out);
}

// round 15
// speedup vs baseline: 1.0356x; 1.0356x over previous
#include <cuda_runtime.h>
#include <cuda_fp16.h>
#include <math.h>
#include <stdint.h>

#define BB 64
#define TT 4096
#define CC 256
#define HH 4
#define HD 64
#define LN_EPS 1e-5f
#define NSPLIT 16
#define TS (TT / NSPLIT)   // 256 t-rows per split

// W image: per head 64 rows x 264 (padded) fp16 = 33792 B = 2112 uint4
#define WPAD 264
#define W_U4_PER_H 2112

// smem layout for k_scores_mma (bytes) — M=128 tile
#define SMEM_X 0
#define SMEM_W (128 * WPAD * 2)                 // 67584
#define SMEM_SC_TOTAL (SMEM_W + 64 * WPAD * 2)  // 101376

// ---------------------------------------------------------------------------
// scratch globals (no allocations allowed)
// ---------------------------------------------------------------------------
__device__ float  g_scores[BB * HH * TT];        // 4 MB (reused as raw-out later)
__device__ float  g_ctx[BB * NSPLIT * HH * CC];  // 16 MB
__device__ float  g_multi[BB * HH * CC];         // 256 KB
__device__ float2 g_stat[BB * HH];               // per-(b,h) {max, 1/sum}
__device__ uint4  g_wimg[HH * W_U4_PER_H];       // fp16 W1^T images, padded rows

__device__ __forceinline__ uint32_t smem_to_u32(const void* p) {
    uint32_t a;
    asm("{ .reg .u64 t; cvta.to.shared.u64 t, %1; cvt.u32.u64 %0, t; }" : "=r"(a) : "l"(p));
    return a;
}
__device__ __forceinline__ float tanh_fast(float x) {
    float y;
    asm("tanh.approx.f32 %0, %1;" : "=f"(y) : "f"(x));
    return y;
}

#define LDMATRIX_X4(r0, r1, r2, r3, addr) \
    asm volatile("ldmatrix.sync.aligned.m8n8.x4.shared.b16 {%0,%1,%2,%3}, [%4];" \
                 : "=r"(r0), "=r"(r1), "=r"(r2), "=r"(r3) : "r"(addr))

#define MMA_16816(c, a0, a1, a2, a3, b0, b1) \
    asm volatile("mma.sync.aligned.m16n8k16.row.col.f32.f16.f16.f32 " \
                 "{%0,%1,%2,%3}, {%4,%5,%6,%7}, {%8,%9}, {%0,%1,%2,%3};" \
                 : "+f"((c)[0]), "+f"((c)[1]), "+f"((c)[2]), "+f"((c)[3]) \
                 : "r"(a0), "r"(a1), "r"(a2), "r"(a3), "r"(b0), "r"(b1))

// ---------------------------------------------------------------------------
// Prep: W1[h] (C x HD, d contiguous) -> fp16 (d-row, c-col) padded image
// ---------------------------------------------------------------------------
__global__ void k_prepw(const float* __restrict__ W1) {
    const int h = blockIdx.x;
    __half* img = (__half*)g_wimg + (size_t)h * (64 * WPAD);
    for (int i = threadIdx.x; i < CC * HD; i += blockDim.x) {
        int c = i >> 6, d = i & 63;
        img[d * WPAD + c] = __float2half_rn(W1[(size_t)h * CC * HD + i]);
    }
}

// ---------------------------------------------------------------------------
// Stage 1 (mma.sync fp16): scores[b][h][t] = w2[h].tanh(x[b][t]@W1[h]+b1[h])
// CTA = 128 t-rows x 1 batch; 8 warps. (R13 proven version, no mirror.)
// ---------------------------------------------------------------------------
__global__ __launch_bounds__(256, 2) void k_scores_mma(
    const float* __restrict__ x, const float* __restrict__ b1,
    const float* __restrict__ w2)
{
    extern __shared__ char smem[];
    const int tid = threadIdx.x;
    const int wid = tid >> 5;
    const int lid = tid & 31;
    const int t0 = blockIdx.x * 128;
    const int b  = blockIdx.y;
    const uint32_t sbase = smem_to_u32(smem);

    // ---- load X tile (128x256 f32), convert to fp16, padded smem ----
    {
        const float4* xg = (const float4*)(x + ((size_t)b * TT + t0) * CC);
        #pragma unroll
        for (int i = 0; i < 32; i++) {
            int idx = tid + i * 256;
            int m = idx >> 6, c4 = idx & 63;
            float4 v = xg[idx];
            __half2 h0 = __floats2half2_rn(v.x, v.y);
            __half2 h1 = __floats2half2_rn(v.z, v.w);
            uint2 p;
            p.x = *(const uint32_t*)&h0;
            p.y = *(const uint32_t*)&h1;
            *(uint2*)(smem + SMEM_X + m * (WPAD * 2) + c4 * 8) = p;
        }
    }
    // ---- copy W(0) ----
    {
        uint4* dst = (uint4*)(smem + SMEM_W);
        #pragma unroll
        for (int i = 0; i < 9; i++) {
            int j = tid + i * 256;
            if (j < W_U4_PER_H) dst[j] = g_wimg[j];
        }
    }
    __syncthreads();    // X + W0 visible

    // ---- per-lane ldmatrix base addresses ----
    const int lq = lid >> 3;      // quad 0..3
    const int lr = lid & 7;
    const uint32_t a_base = sbase + SMEM_X +
        ((uint32_t)(wid * 16 + lr + ((lq & 1) << 3)) * (WPAD * 2)) + (((lq >> 1) << 3) << 1);
    uint32_t b_base[4];
    #pragma unroll
    for (int g = 0; g < 4; g++)
        b_base[g] = sbase + SMEM_W +
            ((uint32_t)((g * 2 + (lq >> 1)) * 8 + lr) * (WPAD * 2)) + (((lq & 1) << 3) << 1);

    const int d0 = (lid & 3) * 2;

    #pragma unroll 1
    for (int h = 0; h < HH; h++) {
        float c[8][4];
        #pragma unroll
        for (int nt = 0; nt < 8; nt++)
            #pragma unroll
            for (int j = 0; j < 4; j++) c[nt][j] = 0.f;

        #pragma unroll 4
        for (int ks = 0; ks < 16; ks++) {
            uint32_t a0, a1, a2, a3;
            LDMATRIX_X4(a0, a1, a2, a3, a_base + ks * 32);
            uint32_t br[16];
            #pragma unroll
            for (int g = 0; g < 4; g++)
                LDMATRIX_X4(br[g * 4], br[g * 4 + 1], br[g * 4 + 2], br[g * 4 + 3],
                            b_base[g] + ks * 32);
            #pragma unroll
            for (int nt = 0; nt < 8; nt++) {
                int bi = (nt >> 1) * 4 + (nt & 1) * 2;
                MMA_16816(c[nt], a0, a1, a2, a3, br[bi], br[bi + 1]);
            }
        }

        if (h < HH - 1) {
            __syncthreads();   // all warps done reading W(h)
            // ---- issue W(h+1) copy; overlaps the epilogue below ----
            {
                const uint4* src = g_wimg + (h + 1) * W_U4_PER_H;
                uint4* dst = (uint4*)(smem + SMEM_W);
                #pragma unroll
                for (int i = 0; i < 9; i++) {
                    int j = tid + i * 256;
                    if (j < W_U4_PER_H) dst[j] = src[j];
                }
            }
        }

        // ---- epilogue: + b1, HW tanh, dot w2, reduce over lane quads ----
        float s0 = 0.f, s1 = 0.f;
        #pragma unroll
        for (int nt = 0; nt < 8; nt++) {
            #pragma unroll
            for (int j = 0; j < 2; j++) {
                int d = nt * 8 + d0 + j;
                float bb = __ldg(&b1[h * HD + d]);
                float ww = __ldg(&w2[h * HD + d]);
                s0 += tanh_fast(c[nt][j] + bb) * ww;       // row = groupID
                s1 += tanh_fast(c[nt][2 + j] + bb) * ww;   // row = groupID + 8
            }
        }
        s0 += __shfl_xor_sync(0xffffffffu, s0, 1);
        s0 += __shfl_xor_sync(0xffffffffu, s0, 2);
        s1 += __shfl_xor_sync(0xffffffffu, s1, 1);
        s1 += __shfl_xor_sync(0xffffffffu, s1, 2);
        if ((lid & 3) == 0) {
            int r = wid * 16 + (lid >> 2);
            float* sc = g_scores + ((size_t)(b * HH + h)) * TT + t0;
            sc[r]     = s0;
            sc[r + 8] = s1;
        }

        if (h < HH - 1) __syncthreads();   // W(h+1) ready for next kloop
    }
}

// ---------------------------------------------------------------------------
// Stage 2: softmax stats (max, 1/sum) per (b,h). grid = B*H.
// ---------------------------------------------------------------------------
__global__ __launch_bounds__(256, 1) void k_stats()
{
    const int bh  = blockIdx.x;
    const int tid = threadIdx.x;
    const float* s = g_scores + (size_t)bh * TT;
    __shared__ float red[256];

    float loc[16];
    float m = -1e30f;
    #pragma unroll
    for (int i = 0; i < 16; i++) { loc[i] = s[tid + i * 256]; m = fmaxf(m, loc[i]); }
    red[tid] = m; __syncthreads();
    for (int st = 128; st > 0; st >>= 1) {
        if (tid < st) red[tid] = fmaxf(red[tid], red[tid + st]);
        __syncthreads();
    }
    m = red[0]; __syncthreads();

    float sum = 0.f;
    #pragma unroll
    for (int i = 0; i < 16; i++) sum += __expf(loc[i] - m);
    red[tid] = sum; __syncthreads();
    for (int st = 128; st > 0; st >>= 1) {
        if (tid < st) red[tid] += red[tid + st];
        __syncthreads();
    }
    if (tid == 0) g_stat[bh] = make_float2(m, 1.f / red[0]);
}

// ---------------------------------------------------------------------------
// Stage 3: weights (from scores+stats) + partial contexts; writes weights out.
// 256 threads = 4 row-groups x 64 channel-quads; float4 loads for MLP.
// ---------------------------------------------------------------------------
__global__ __launch_bounds__(256, 2) void k_ctx(
    const float* __restrict__ x, float* __restrict__ wout)
{
    const int split = blockIdx.x;
    const int b     = blockIdx.y;
    const int tid   = threadIdx.x;
    const int grp   = tid >> 6;     // 0..3
    const int ch    = tid & 63;     // float4-column
    __shared__ float ws[HH][TS];            // 4 KB
    __shared__ float red[4][HH][CC];        // 16 KB

    const int tbase = split * TS;
    #pragma unroll
    for (int i = tid; i < HH * TS; i += 256) {
        int hh = i >> 8, tt = i & (TS - 1);
        float2 st = g_stat[b * HH + hh];
        float sv = g_scores[((size_t)(b * HH + hh)) * TT + tbase + tt];
        float w = __expf(sv - st.x) * st.y;
        ws[hh][tt] = w;
        wout[((size_t)(b * HH + hh)) * TT + tbase + tt] = w;
    }
    __syncthreads();

    float4 acc[HH] = {};
    const float4* xp = (const float4*)(x + ((size_t)b * TT + tbase) * CC) + ch;
    #pragma unroll 4
    for (int tt = grp; tt < TS; tt += 4) {
        float4 xv = xp[(size_t)tt * 64];
        #pragma unroll
        for (int h = 0; h < HH; h++) {
            float w = ws[h][tt];
            acc[h].x += w * xv.x; acc[h].y += w * xv.y;
            acc[h].z += w * xv.z; acc[h].w += w * xv.w;
        }
    }
    #pragma unroll
    for (int h = 0; h < HH; h++)
        *(float4*)&red[grp][h][ch * 4] = acc[h];
    __syncthreads();

    for (int n = tid; n < HH * CC; n += 256) {
        int h = n >> 8, c = n & 255;
        float s = red[0][h][c] + red[1][h][c] + red[2][h][c] + red[3][h][c];
        g_ctx[(((size_t)(b * NSPLIT + split)) * HH + h) * CC + c] = s;
    }
}

// ---------------------------------------------------------------------------
// Stage 4a: reduce splits -> g_multi[b][h*C+c]. grid = B.
// ---------------------------------------------------------------------------
__global__ __launch_bounds__(256, 1) void k_redctx()
{
    const int b   = blockIdx.x;
    const int tid = threadIdx.x;
    #pragma unroll
    for (int rep = 0; rep < 4; rep++) {
        int n = tid + rep * 256;
        float s = 0.f;
        #pragma unroll
        for (int sp = 0; sp < NSPLIT; sp++)
            s += g_ctx[((size_t)(b * NSPLIT + sp)) * (HH * CC) + n];
        g_multi[(size_t)b * (HH * CC) + n] = s;
    }
}

// ---------------------------------------------------------------------------
// Stage 4b: projection, 8 batches per CTA. grid (8 col-tiles, 8 b-groups).
// Raw out -> g_scores scratch (safe: stats+ctx already consumed scores).
// ---------------------------------------------------------------------------
__global__ __launch_bounds__(256, 1) void k_proj(
    const float* __restrict__ Wo, const float* __restrict__ bo)
{
    const int ct  = blockIdx.x;   // 0..7 (32 cols each)
    const int bg  = blockIdx.y;   // 0..7 (8 batches each)
    const int tid = threadIdx.x;
    __shared__ float multi[8][HH * CC];     // 32 KB

    for (int i = tid; i < 8 * HH * CC; i += 256) {
        int bb = i >> 10, n = i & 1023;
        multi[bb][n] = g_multi[(size_t)(bg * 8 + bb) * (HH * CC) + n];
    }
    __syncthreads();

    const int col   = ct * 32 + (tid >> 3);
    const int lane8 = tid & 7;
    const float* wr = Wo + (size_t)col * (HH * CC);
    float v[8] = {};
    #pragma unroll 4
    for (int k = lane8 * 4; k < HH * CC; k += 32) {
        float4 w4 = *(const float4*)&wr[k];
        #pragma unroll
        for (int bb = 0; bb < 8; bb++) {
            v[bb] += w4.x * multi[bb][k]     + w4.y * multi[bb][k + 1]
                   + w4.z * multi[bb][k + 2] + w4.w * multi[bb][k + 3];
        }
    }
    #pragma unroll
    for (int bb = 0; bb < 8; bb++) {
        v[bb] += __shfl_down_sync(0xffffffffu, v[bb], 4, 8);
        v[bb] += __shfl_down_sync(0xffffffffu, v[bb], 2, 8);
        v[bb] += __shfl_down_sync(0xffffffffu, v[bb], 1, 8);
    }
    if (lane8 == 0) {
        const float bv = bo[col];
        #pragma unroll
        for (int bb = 0; bb < 8; bb++)
            g_scores[(size_t)(bg * 8 + bb) * CC + col] = v[bb] + bv;
    }
}

// ---------------------------------------------------------------------------
// Stage 4c: LayerNorm. grid = B.
// ---------------------------------------------------------------------------
__global__ __launch_bounds__(256, 1) void k_ln(
    const float* __restrict__ gamma, const float* __restrict__ beta,
    float* __restrict__ out)
{
    const int b   = blockIdx.x;
    const int tid = threadIdx.x;
    __shared__ float red[256];
    const float v = g_scores[(size_t)b * CC + tid];

    red[tid] = v; __syncthreads();
    for (int st = 128; st > 0; st >>= 1) {
        if (tid < st) red[tid] += red[tid + st];
        __syncthreads();
    }
    const float mu = red[0] * (1.f / CC); __syncthreads();
    const float d = v - mu;
    red[tid] = d * d; __syncthreads();
    for (int st = 128; st > 0; st >>= 1) {
        if (tid < st) red[tid] += red[tid + st];
        __syncthreads();
    }
    const float var = red[0] * (1.f / CC);
    out[(size_t)b * CC + tid] = d * rsqrtf(var + LN_EPS) * gamma[tid] + beta[tid];
}

// ---------------------------------------------------------------------------
extern "C" void kernel_launch(void* const* d_in, const int* in_sizes, int n_in,
                              void* d_out, int out_size)
{
    const float* x     = (const float*)d_in[0];
    const float* W1    = (const float*)d_in[1];
    const float* b1    = (const float*)d_in[2];
    const float* w2    = (const float*)d_in[3];
    const float* Wo    = (const float*)d_in[4];
    const float* bo    = (const float*)d_in[5];
    const float* gamma = (const float*)d_in[6];
    const float* beta  = (const float*)d_in[7];

    float* out = (float*)d_out;           // (B, C)
    float* wts = out + BB * CC;           // (B, H, T)

    cudaFuncSetAttribute(k_scores_mma, cudaFuncAttributeMaxDynamicSharedMemorySize,
                         SMEM_SC_TOTAL);

    k_prepw     <<<HH, 256>>>(W1);
    k_scores_mma<<<dim3(TT / 128, BB), 256, SMEM_SC_TOTAL>>>(x, b1, w2);
    k_stats     <<<BB * HH, 256>>>();
    k_ctx       <<<dim3(NSPLIT, BB), 256>>>(x, wts);
    k_redctx    <<<BB, 256>>>();
    k_proj      <<<dim3(8, 8), 256>>>(Wo, bo);
    k_ln        <<<BB, 256>>>(gamma, beta, out);
}

// round 16
// speedup vs baseline: 1.1313x; 1.0924x over previous
#include <cuda_runtime.h>
#include <cuda_fp16.h>
#include <math.h>
#include <stdint.h>

#define BB 64
#define TT 4096
#define CC 256
#define HH 4
#define HD 64
#define LN_EPS 1e-5f
#define NSPLIT 16
#define TS (TT / NSPLIT)   // 256 t-rows per split

// W image: per head 64 rows x 264 (padded) fp16 = 33792 B = 2112 uint4
#define WPAD 264
#define W_U4_PER_H 2112

// smem layout for k_scores_mma (bytes) — M=128 tile
#define SMEM_X 0
#define SMEM_W (128 * WPAD * 2)                 // 67584
#define SMEM_SC_TOTAL (SMEM_W + 64 * WPAD * 2)  // 101376

// ---------------------------------------------------------------------------
// scratch globals (no allocations allowed)
// ---------------------------------------------------------------------------
__device__ float  g_scores[BB * HH * TT];        // 4 MB (reused as raw-out later)
__device__ float  g_ctx[BB * NSPLIT * HH * CC];  // 16 MB
__device__ float2 g_stat[BB * HH];               // per-(b,h) {max, 1/sum}
__device__ uint4  g_wimg[HH * W_U4_PER_H];       // fp16 W1^T images, padded rows

__device__ __forceinline__ uint32_t smem_to_u32(const void* p) {
    uint32_t a;
    asm("{ .reg .u64 t; cvta.to.shared.u64 t, %1; cvt.u32.u64 %0, t; }" : "=r"(a) : "l"(p));
    return a;
}
__device__ __forceinline__ float tanh_fast(float x) {
    float y;
    asm("tanh.approx.f32 %0, %1;" : "=f"(y) : "f"(x));
    return y;
}

#define LDMATRIX_X4(r0, r1, r2, r3, addr) \
    asm volatile("ldmatrix.sync.aligned.m8n8.x4.shared.b16 {%0,%1,%2,%3}, [%4];" \
                 : "=r"(r0), "=r"(r1), "=r"(r2), "=r"(r3) : "r"(addr))

#define MMA_16816(c, a0, a1, a2, a3, b0, b1) \
    asm volatile("mma.sync.aligned.m16n8k16.row.col.f32.f16.f16.f32 " \
                 "{%0,%1,%2,%3}, {%4,%5,%6,%7}, {%8,%9}, {%0,%1,%2,%3};" \
                 : "+f"((c)[0]), "+f"((c)[1]), "+f"((c)[2]), "+f"((c)[3]) \
                 : "r"(a0), "r"(a1), "r"(a2), "r"(a3), "r"(b0), "r"(b1))

// ---------------------------------------------------------------------------
// Prep: W1[h] (C x HD, d contiguous) -> fp16 (d-row, c-col) padded image
// 32 CTAs: 8 per head, each covers 2048 of 16384 elements.
// ---------------------------------------------------------------------------
__global__ void k_prepw(const float* __restrict__ W1) {
    const int h   = blockIdx.x >> 3;
    const int sub = blockIdx.x & 7;
    __half* img = (__half*)g_wimg + (size_t)h * (64 * WPAD);
    const int base = sub * 2048;
    for (int k = threadIdx.x; k < 2048; k += blockDim.x) {
        int i = base + k;
        int c = i >> 6, d = i & 63;
        img[d * WPAD + c] = __float2half_rn(W1[(size_t)h * CC * HD + i]);
    }
}

// ---------------------------------------------------------------------------
// Stage 1 (mma.sync fp16): scores[b][h][t] = w2[h].tanh(x[b][t]@W1[h]+b1[h])
// CTA = 128 t-rows x 1 batch; 8 warps. (R13 proven version.)
// ---------------------------------------------------------------------------
__global__ __launch_bounds__(256, 2) void k_scores_mma(
    const float* __restrict__ x, const float* __restrict__ b1,
    const float* __restrict__ w2)
{
    extern __shared__ char smem[];
    const int tid = threadIdx.x;
    const int wid = tid >> 5;
    const int lid = tid & 31;
    const int t0 = blockIdx.x * 128;
    const int b  = blockIdx.y;
    const uint32_t sbase = smem_to_u32(smem);

    // ---- load X tile (128x256 f32), convert to fp16, padded smem ----
    {
        const float4* xg = (const float4*)(x + ((size_t)b * TT + t0) * CC);
        #pragma unroll
        for (int i = 0; i < 32; i++) {
            int idx = tid + i * 256;
            int m = idx >> 6, c4 = idx & 63;
            float4 v = xg[idx];
            __half2 h0 = __floats2half2_rn(v.x, v.y);
            __half2 h1 = __floats2half2_rn(v.z, v.w);
            uint2 p;
            p.x = *(const uint32_t*)&h0;
            p.y = *(const uint32_t*)&h1;
            *(uint2*)(smem + SMEM_X + m * (WPAD * 2) + c4 * 8) = p;
        }
    }
    // ---- copy W(0) ----
    {
        uint4* dst = (uint4*)(smem + SMEM_W);
        #pragma unroll
        for (int i = 0; i < 9; i++) {
            int j = tid + i * 256;
            if (j < W_U4_PER_H) dst[j] = g_wimg[j];
        }
    }
    __syncthreads();    // X + W0 visible

    // ---- per-lane ldmatrix base addresses ----
    const int lq = lid >> 3;      // quad 0..3
    const int lr = lid & 7;
    const uint32_t a_base = sbase + SMEM_X +
        ((uint32_t)(wid * 16 + lr + ((lq & 1) << 3)) * (WPAD * 2)) + (((lq >> 1) << 3) << 1);
    uint32_t b_base[4];
    #pragma unroll
    for (int g = 0; g < 4; g++)
        b_base[g] = sbase + SMEM_W +
            ((uint32_t)((g * 2 + (lq >> 1)) * 8 + lr) * (WPAD * 2)) + (((lq & 1) << 3) << 1);

    const int d0 = (lid & 3) * 2;

    #pragma unroll 1
    for (int h = 0; h < HH; h++) {
        float c[8][4];
        #pragma unroll
        for (int nt = 0; nt < 8; nt++)
            #pragma unroll
            for (int j = 0; j < 4; j++) c[nt][j] = 0.f;

        #pragma unroll 4
        for (int ks = 0; ks < 16; ks++) {
            uint32_t a0, a1, a2, a3;
            LDMATRIX_X4(a0, a1, a2, a3, a_base + ks * 32);
            uint32_t br[16];
            #pragma unroll
            for (int g = 0; g < 4; g++)
                LDMATRIX_X4(br[g * 4], br[g * 4 + 1], br[g * 4 + 2], br[g * 4 + 3],
                            b_base[g] + ks * 32);
            #pragma unroll
            for (int nt = 0; nt < 8; nt++) {
                int bi = (nt >> 1) * 4 + (nt & 1) * 2;
                MMA_16816(c[nt], a0, a1, a2, a3, br[bi], br[bi + 1]);
            }
        }

        if (h < HH - 1) {
            __syncthreads();   // all warps done reading W(h)
            // ---- issue W(h+1) copy; overlaps the epilogue below ----
            {
                const uint4* src = g_wimg + (h + 1) * W_U4_PER_H;
                uint4* dst = (uint4*)(smem + SMEM_W);
                #pragma unroll
                for (int i = 0; i < 9; i++) {
                    int j = tid + i * 256;
                    if (j < W_U4_PER_H) dst[j] = src[j];
                }
            }
        }

        // ---- epilogue: + b1, HW tanh, dot w2, reduce over lane quads ----
        float s0 = 0.f, s1 = 0.f;
        #pragma unroll
        for (int nt = 0; nt < 8; nt++) {
            #pragma unroll
            for (int j = 0; j < 2; j++) {
                int d = nt * 8 + d0 + j;
                float bb = __ldg(&b1[h * HD + d]);
                float ww = __ldg(&w2[h * HD + d]);
                s0 += tanh_fast(c[nt][j] + bb) * ww;       // row = groupID
                s1 += tanh_fast(c[nt][2 + j] + bb) * ww;   // row = groupID + 8
            }
        }
        s0 += __shfl_xor_sync(0xffffffffu, s0, 1);
        s0 += __shfl_xor_sync(0xffffffffu, s0, 2);
        s1 += __shfl_xor_sync(0xffffffffu, s1, 1);
        s1 += __shfl_xor_sync(0xffffffffu, s1, 2);
        if ((lid & 3) == 0) {
            int r = wid * 16 + (lid >> 2);
            float* sc = g_scores + ((size_t)(b * HH + h)) * TT + t0;
            sc[r]     = s0;
            sc[r + 8] = s1;
        }

        if (h < HH - 1) __syncthreads();   // W(h+1) ready for next kloop
    }
}

// ---------------------------------------------------------------------------
// Stage 2: softmax stats (max, 1/sum) per (b,h). grid = B*H.
// ---------------------------------------------------------------------------
__global__ __launch_bounds__(256, 1) void k_stats()
{
    const int bh  = blockIdx.x;
    const int tid = threadIdx.x;
    const float* s = g_scores + (size_t)bh * TT;
    __shared__ float red[256];

    float loc[16];
    float m = -1e30f;
    #pragma unroll
    for (int i = 0; i < 16; i++) { loc[i] = s[tid + i * 256]; m = fmaxf(m, loc[i]); }
    red[tid] = m; __syncthreads();
    for (int st = 128; st > 0; st >>= 1) {
        if (tid < st) red[tid] = fmaxf(red[tid], red[tid + st]);
        __syncthreads();
    }
    m = red[0]; __syncthreads();

    float sum = 0.f;
    #pragma unroll
    for (int i = 0; i < 16; i++) sum += __expf(loc[i] - m);
    red[tid] = sum; __syncthreads();
    for (int st = 128; st > 0; st >>= 1) {
        if (tid < st) red[tid] += red[tid + st];
        __syncthreads();
    }
    if (tid == 0) g_stat[bh] = make_float2(m, 1.f / red[0]);
}

// ---------------------------------------------------------------------------
// Stage 3: weights (scores+stats) + partial contexts; also writes weights out.
// 256 threads = 4 row-groups x 64 channel-quads; float4 loads for MLP.
// ---------------------------------------------------------------------------
__global__ __launch_bounds__(256, 2) void k_ctx(
    const float* __restrict__ x, float* __restrict__ wout)
{
    const int split = blockIdx.x;
    const int b     = blockIdx.y;
    const int tid   = threadIdx.x;
    const int grp   = tid >> 6;     // 0..3
    const int ch    = tid & 63;     // float4-column
    __shared__ float ws[HH][TS];            // 4 KB
    __shared__ float red[4][HH][CC];        // 16 KB

    const int tbase = split * TS;
    #pragma unroll
    for (int i = tid; i < HH * TS; i += 256) {
        int hh = i >> 8, tt = i & (TS - 1);
        float2 st = g_stat[b * HH + hh];
        float sv = g_scores[((size_t)(b * HH + hh)) * TT + tbase + tt];
        float w = __expf(sv - st.x) * st.y;
        ws[hh][tt] = w;
        wout[((size_t)(b * HH + hh)) * TT + tbase + tt] = w;
    }
    __syncthreads();

    float4 acc[HH] = {};
    const float4* xp = (const float4*)(x + ((size_t)b * TT + tbase) * CC) + ch;
    #pragma unroll 4
    for (int tt = grp; tt < TS; tt += 4) {
        float4 xv = xp[(size_t)tt * 64];
        #pragma unroll
        for (int h = 0; h < HH; h++) {
            float w = ws[h][tt];
            acc[h].x += w * xv.x; acc[h].y += w * xv.y;
            acc[h].z += w * xv.z; acc[h].w += w * xv.w;
        }
    }
    #pragma unroll
    for (int h = 0; h < HH; h++)
        *(float4*)&red[grp][h][ch * 4] = acc[h];
    __syncthreads();

    for (int n = tid; n < HH * CC; n += 256) {
        int h = n >> 8, c = n & 255;
        float s = red[0][h][c] + red[1][h][c] + red[2][h][c] + red[3][h][c];
        g_ctx[(((size_t)(b * NSPLIT + split)) * HH + h) * CC + c] = s;
    }
}

// ---------------------------------------------------------------------------
// Stage 4a: projection. grid (8 col-tiles, B). Raw out -> g_scores scratch.
// (512-CTA BW-bound version — measured faster than 64-CTA Wo-tiled variant.)
// ---------------------------------------------------------------------------
__global__ __launch_bounds__(256, 1) void k_proj(
    const float* __restrict__ Wo, const float* __restrict__ bo)
{
    const int ct  = blockIdx.x;   // 0..7 (32 cols each)
    const int b   = blockIdx.y;
    const int tid = threadIdx.x;
    __shared__ float multi[HH * CC];

    for (int n = tid; n < HH * CC; n += 256) {
        float s = 0.f;
        #pragma unroll
        for (int sp = 0; sp < NSPLIT; sp++)
            s += g_ctx[((size_t)(b * NSPLIT + sp)) * (HH * CC) + n];
        multi[n] = s;
    }
    __syncthreads();

    const int col   = ct * 32 + (tid >> 3);
    const int lane8 = tid & 7;
    const float* wr = Wo + (size_t)col * (HH * CC);
    float v = 0.f;
    #pragma unroll 4
    for (int k = lane8 * 4; k < HH * CC; k += 32) {
        float4 w4 = *(const float4*)&wr[k];
        v += w4.x * multi[k] + w4.y * multi[k + 1] + w4.z * multi[k + 2] + w4.w * multi[k + 3];
    }
    v += __shfl_down_sync(0xffffffffu, v, 4, 8);
    v += __shfl_down_sync(0xffffffffu, v, 2, 8);
    v += __shfl_down_sync(0xffffffffu, v, 1, 8);
    if (lane8 == 0) g_scores[(size_t)b * CC + col] = v + bo[col];
}

// ---------------------------------------------------------------------------
// Stage 4b: LayerNorm. grid = B.
// ---------------------------------------------------------------------------
__global__ __launch_bounds__(256, 1) void k_ln(
    const float* __restrict__ gamma, const float* __restrict__ beta,
    float* __restrict__ out)
{
    const int b   = blockIdx.x;
    const int tid = threadIdx.x;
    __shared__ float red[256];
    const float v = g_scores[(size_t)b * CC + tid];

    red[tid] = v; __syncthreads();
    for (int st = 128; st > 0; st >>= 1) {
        if (tid < st) red[tid] += red[tid + st];
        __syncthreads();
    }
    const float mu = red[0] * (1.f / CC); __syncthreads();
    const float d = v - mu;
    red[tid] = d * d; __syncthreads();
    for (int st = 128; st > 0; st >>= 1) {
        if (tid < st) red[tid] += red[tid + st];
        __syncthreads();
    }
    const float var = red[0] * (1.f / CC);
    out[(size_t)b * CC + tid] = d * rsqrtf(var + LN_EPS) * gamma[tid] + beta[tid];
}

// ---------------------------------------------------------------------------
extern "C" void kernel_launch(void* const* d_in, const int* in_sizes, int n_in,
                              void* d_out, int out_size)
{
    const float* x     = (const float*)d_in[0];
    const float* W1    = (const float*)d_in[1];
    const float* b1    = (const float*)d_in[2];
    const float* w2    = (const float*)d_in[3];
    const float* Wo    = (const float*)d_in[4];
    const float* bo    = (const float*)d_in[5];
    const float* gamma = (const float*)d_in[6];
    const float* beta  = (const float*)d_in[7];

    float* out = (float*)d_out;           // (B, C)
    float* wts = out + BB * CC;           // (B, H, T)

    cudaFuncSetAttribute(k_scores_mma, cudaFuncAttributeMaxDynamicSharedMemorySize,
                         SMEM_SC_TOTAL);

    k_prepw     <<<32, 256>>>(W1);
    k_scores_mma<<<dim3(TT / 128, BB), 256, SMEM_SC_TOTAL>>>(x, b1, w2);
    k_stats     <<<BB * HH, 256>>>();
    k_ctx       <<<dim3(NSPLIT, BB), 256>>>(x, wts);
    k_proj      <<<dim3(8, BB), 256>>>(Wo, bo);
    k_ln        <<<BB, 256>>>(gamma, beta, out);
}

// round 17
// speedup vs baseline: 1.2078x; 1.0676x over previous
#include <cuda_runtime.h>
#include <cuda_fp16.h>
#include <math.h>
#include <stdint.h>

#define BB 64
#define TT 4096
#define CC 256
#define HH 4
#define HD 64
#define LN_EPS 1e-5f
#define NSPLIT 16
#define TS (TT / NSPLIT)   // 256 t-rows per split

// W image: per head 64 rows x 264 (padded) fp16 = 33792 B = 2112 uint4
#define WPAD 264
#define W_U4_PER_H 2112

// smem layout for k_scores_mma (bytes) — M=128 tile
#define SMEM_X 0
#define SMEM_W (128 * WPAD * 2)                 // 67584
#define SMEM_SC_TOTAL (SMEM_W + 64 * WPAD * 2)  // 101376

// ---------------------------------------------------------------------------
// scratch globals (no allocations allowed)
// ---------------------------------------------------------------------------
__device__ float  g_scores[BB * HH * TT];        // 4 MB (reused as raw-out later)
__device__ float  g_ctx[BB * NSPLIT * HH * CC];  // 16 MB
__device__ float2 g_stat[BB * HH];               // per-(b,h) {max, 1/sum}
__device__ uint4  g_wimg[HH * W_U4_PER_H];       // fp16 W1^T images, padded rows

__device__ __forceinline__ uint32_t smem_to_u32(const void* p) {
    uint32_t a;
    asm("{ .reg .u64 t; cvta.to.shared.u64 t, %1; cvt.u32.u64 %0, t; }" : "=r"(a) : "l"(p));
    return a;
}
__device__ __forceinline__ float tanh_fast(float x) {
    float y;
    asm("tanh.approx.f32 %0, %1;" : "=f"(y) : "f"(x));
    return y;
}
__device__ __forceinline__ void cp_async16(uint32_t smem_dst, const void* gptr) {
    asm volatile("cp.async.cg.shared.global [%0], [%1], 16;"
                 :: "r"(smem_dst), "l"(gptr) : "memory");
}
__device__ __forceinline__ void cp_async_commit() {
    asm volatile("cp.async.commit_group;" ::: "memory");
}
__device__ __forceinline__ void cp_async_wait0() {
    asm volatile("cp.async.wait_group 0;" ::: "memory");
}

#define LDMATRIX_X4(r0, r1, r2, r3, addr) \
    asm volatile("ldmatrix.sync.aligned.m8n8.x4.shared.b16 {%0,%1,%2,%3}, [%4];" \
                 : "=r"(r0), "=r"(r1), "=r"(r2), "=r"(r3) : "r"(addr))

#define MMA_16816(c, a0, a1, a2, a3, b0, b1) \
    asm volatile("mma.sync.aligned.m16n8k16.row.col.f32.f16.f16.f32 " \
                 "{%0,%1,%2,%3}, {%4,%5,%6,%7}, {%8,%9}, {%0,%1,%2,%3};" \
                 : "+f"((c)[0]), "+f"((c)[1]), "+f"((c)[2]), "+f"((c)[3]) \
                 : "r"(a0), "r"(a1), "r"(a2), "r"(a3), "r"(b0), "r"(b1))

// ---------------------------------------------------------------------------
// Prep: W1[h] (C x HD, d contiguous) -> fp16 (d-row, c-col) padded image
// 32 CTAs: 8 per head, each covers 2048 of 16384 elements.
// ---------------------------------------------------------------------------
__global__ void k_prepw(const float* __restrict__ W1) {
    const int h   = blockIdx.x >> 3;
    const int sub = blockIdx.x & 7;
    __half* img = (__half*)g_wimg + (size_t)h * (64 * WPAD);
    const int base = sub * 2048;
    for (int k = threadIdx.x; k < 2048; k += blockDim.x) {
        int i = base + k;
        int c = i >> 6, d = i & 63;
        img[d * WPAD + c] = __float2half_rn(W1[(size_t)h * CC * HD + i]);
    }
}

// ---------------------------------------------------------------------------
// Stage 1 (mma.sync fp16): scores[b][h][t] = w2[h].tanh(x[b][t]@W1[h]+b1[h])
// CTA = 128 t-rows x 1 batch; 8 warps. W copies via cp.async so they overlap
// the X prologue (W0) and the tanh epilogue (W1..W3).
// ---------------------------------------------------------------------------
__global__ __launch_bounds__(256, 2) void k_scores_mma(
    const float* __restrict__ x, const float* __restrict__ b1,
    const float* __restrict__ w2)
{
    extern __shared__ char smem[];
    const int tid = threadIdx.x;
    const int wid = tid >> 5;
    const int lid = tid & 31;
    const int t0 = blockIdx.x * 128;
    const int b  = blockIdx.y;
    const uint32_t sbase = smem_to_u32(smem);

    // ---- kick off W(0) copy (async), then do X load/convert over it ----
    {
        const uint32_t wdst = sbase + SMEM_W;
        #pragma unroll
        for (int i = 0; i < 9; i++) {
            int j = tid + i * 256;
            if (j < W_U4_PER_H) cp_async16(wdst + j * 16, g_wimg + j);
        }
        cp_async_commit();
    }
    // ---- load X tile (128x256 f32), convert to fp16, padded smem ----
    {
        const float4* xg = (const float4*)(x + ((size_t)b * TT + t0) * CC);
        #pragma unroll
        for (int i = 0; i < 32; i++) {
            int idx = tid + i * 256;
            int m = idx >> 6, c4 = idx & 63;
            float4 v = xg[idx];
            __half2 h0 = __floats2half2_rn(v.x, v.y);
            __half2 h1 = __floats2half2_rn(v.z, v.w);
            uint2 p;
            p.x = *(const uint32_t*)&h0;
            p.y = *(const uint32_t*)&h1;
            *(uint2*)(smem + SMEM_X + m * (WPAD * 2) + c4 * 8) = p;
        }
    }
    cp_async_wait0();
    __syncthreads();    // X + W0 visible

    // ---- per-lane ldmatrix base addresses ----
    const int lq = lid >> 3;      // quad 0..3
    const int lr = lid & 7;
    const uint32_t a_base = sbase + SMEM_X +
        ((uint32_t)(wid * 16 + lr + ((lq & 1) << 3)) * (WPAD * 2)) + (((lq >> 1) << 3) << 1);
    uint32_t b_base[4];
    #pragma unroll
    for (int g = 0; g < 4; g++)
        b_base[g] = sbase + SMEM_W +
            ((uint32_t)((g * 2 + (lq >> 1)) * 8 + lr) * (WPAD * 2)) + (((lq & 1) << 3) << 1);

    const int d0 = (lid & 3) * 2;

    #pragma unroll 1
    for (int h = 0; h < HH; h++) {
        float c[8][4];
        #pragma unroll
        for (int nt = 0; nt < 8; nt++)
            #pragma unroll
            for (int j = 0; j < 4; j++) c[nt][j] = 0.f;

        #pragma unroll 4
        for (int ks = 0; ks < 16; ks++) {
            uint32_t a0, a1, a2, a3;
            LDMATRIX_X4(a0, a1, a2, a3, a_base + ks * 32);
            uint32_t br[16];
            #pragma unroll
            for (int g = 0; g < 4; g++)
                LDMATRIX_X4(br[g * 4], br[g * 4 + 1], br[g * 4 + 2], br[g * 4 + 3],
                            b_base[g] + ks * 32);
            #pragma unroll
            for (int nt = 0; nt < 8; nt++) {
                int bi = (nt >> 1) * 4 + (nt & 1) * 2;
                MMA_16816(c[nt], a0, a1, a2, a3, br[bi], br[bi + 1]);
            }
        }

        if (h < HH - 1) {
            __syncthreads();   // all warps done reading W(h)
            // ---- async W(h+1) copy; drains under the epilogue below ----
            {
                const uint4* src = g_wimg + (h + 1) * W_U4_PER_H;
                const uint32_t wdst = sbase + SMEM_W;
                #pragma unroll
                for (int i = 0; i < 9; i++) {
                    int j = tid + i * 256;
                    if (j < W_U4_PER_H) cp_async16(wdst + j * 16, src + j);
                }
                cp_async_commit();
            }
        }

        // ---- epilogue: + b1, HW tanh, dot w2, reduce over lane quads ----
        float s0 = 0.f, s1 = 0.f;
        #pragma unroll
        for (int nt = 0; nt < 8; nt++) {
            #pragma unroll
            for (int j = 0; j < 2; j++) {
                int d = nt * 8 + d0 + j;
                float bb = __ldg(&b1[h * HD + d]);
                float ww = __ldg(&w2[h * HD + d]);
                s0 += tanh_fast(c[nt][j] + bb) * ww;       // row = groupID
                s1 += tanh_fast(c[nt][2 + j] + bb) * ww;   // row = groupID + 8
            }
        }
        s0 += __shfl_xor_sync(0xffffffffu, s0, 1);
        s0 += __shfl_xor_sync(0xffffffffu, s0, 2);
        s1 += __shfl_xor_sync(0xffffffffu, s1, 1);
        s1 += __shfl_xor_sync(0xffffffffu, s1, 2);
        if ((lid & 3) == 0) {
            int r = wid * 16 + (lid >> 2);
            float* sc = g_scores + ((size_t)(b * HH + h)) * TT + t0;
            sc[r]     = s0;
            sc[r + 8] = s1;
        }

        if (h < HH - 1) {
            cp_async_wait0();
            __syncthreads();   // W(h+1) ready for next kloop
        }
    }
}

// ---------------------------------------------------------------------------
// Stage 2: softmax stats (max, 1/sum) per (b,h). grid = B*H.
// ---------------------------------------------------------------------------
__global__ __launch_bounds__(256, 1) void k_stats()
{
    const int bh  = blockIdx.x;
    const int tid = threadIdx.x;
    const float* s = g_scores + (size_t)bh * TT;
    __shared__ float red[256];

    float loc[16];
    float m = -1e30f;
    #pragma unroll
    for (int i = 0; i < 16; i++) { loc[i] = s[tid + i * 256]; m = fmaxf(m, loc[i]); }
    red[tid] = m; __syncthreads();
    for (int st = 128; st > 0; st >>= 1) {
        if (tid < st) red[tid] = fmaxf(red[tid], red[tid + st]);
        __syncthreads();
    }
    m = red[0]; __syncthreads();

    float sum = 0.f;
    #pragma unroll
    for (int i = 0; i < 16; i++) sum += __expf(loc[i] - m);
    red[tid] = sum; __syncthreads();
    for (int st = 128; st > 0; st >>= 1) {
        if (tid < st) red[tid] += red[tid + st];
        __syncthreads();
    }
    if (tid == 0) g_stat[bh] = make_float2(m, 1.f / red[0]);
}

// ---------------------------------------------------------------------------
// Stage 3: weights (scores+stats) + partial contexts; also writes weights out.
// 256 threads = 4 row-groups x 64 channel-quads; float4 loads for MLP.
// ---------------------------------------------------------------------------
__global__ __launch_bounds__(256, 4) void k_ctx(
    const float* __restrict__ x, float* __restrict__ wout)
{
    const int split = blockIdx.x;
    const int b     = blockIdx.y;
    const int tid   = threadIdx.x;
    const int grp   = tid >> 6;     // 0..3
    const int ch    = tid & 63;     // float4-column
    __shared__ float ws[HH][TS];            // 4 KB
    __shared__ float red[4][HH][CC];        // 16 KB

    const int tbase = split * TS;
    #pragma unroll
    for (int i = tid; i < HH * TS; i += 256) {
        int hh = i >> 8, tt = i & (TS - 1);
        float2 st = g_stat[b * HH + hh];
        float sv = g_scores[((size_t)(b * HH + hh)) * TT + tbase + tt];
        float w = __expf(sv - st.x) * st.y;
        ws[hh][tt] = w;
        wout[((size_t)(b * HH + hh)) * TT + tbase + tt] = w;
    }
    __syncthreads();

    float4 acc[HH] = {};
    const float4* xp = (const float4*)(x + ((size_t)b * TT + tbase) * CC) + ch;
    #pragma unroll 16
    for (int tt = grp; tt < TS; tt += 4) {
        float4 xv = xp[(size_t)tt * 64];
        #pragma unroll
        for (int h = 0; h < HH; h++) {
            float w = ws[h][tt];
            acc[h].x += w * xv.x; acc[h].y += w * xv.y;
            acc[h].z += w * xv.z; acc[h].w += w * xv.w;
        }
    }
    #pragma unroll
    for (int h = 0; h < HH; h++)
        *(float4*)&red[grp][h][ch * 4] = acc[h];
    __syncthreads();

    for (int n = tid; n < HH * CC; n += 256) {
        int h = n >> 8, c = n & 255;
        float s = red[0][h][c] + red[1][h][c] + red[2][h][c] + red[3][h][c];
        g_ctx[(((size_t)(b * NSPLIT + split)) * HH + h) * CC + c] = s;
    }
}

// ---------------------------------------------------------------------------
// Stage 4a: projection. grid (8 col-tiles, B). Raw out -> g_scores scratch.
// ---------------------------------------------------------------------------
__global__ __launch_bounds__(256, 1) void k_proj(
    const float* __restrict__ Wo, const float* __restrict__ bo)
{
    const int ct  = blockIdx.x;   // 0..7 (32 cols each)
    const int b   = blockIdx.y;
    const int tid = threadIdx.x;
    __shared__ float multi[HH * CC];

    for (int n = tid; n < HH * CC; n += 256) {
        float s = 0.f;
        #pragma unroll
        for (int sp = 0; sp < NSPLIT; sp++)
            s += g_ctx[((size_t)(b * NSPLIT + sp)) * (HH * CC) + n];
        multi[n] = s;
    }
    __syncthreads();

    const int col   = ct * 32 + (tid >> 3);
    const int lane8 = tid & 7;
    const float* wr = Wo + (size_t)col * (HH * CC);
    float v = 0.f;
    #pragma unroll 4
    for (int k = lane8 * 4; k < HH * CC; k += 32) {
        float4 w4 = *(const float4*)&wr[k];
        v += w4.x * multi[k] + w4.y * multi[k + 1] + w4.z * multi[k + 2] + w4.w * multi[k + 3];
    }
    v += __shfl_down_sync(0xffffffffu, v, 4, 8);
    v += __shfl_down_sync(0xffffffffu, v, 2, 8);
    v += __shfl_down_sync(0xffffffffu, v, 1, 8);
    if (lane8 == 0) g_scores[(size_t)b * CC + col] = v + bo[col];
}

// ---------------------------------------------------------------------------
// Stage 4b: LayerNorm. grid = B.
// ---------------------------------------------------------------------------
__global__ __launch_bounds__(256, 1) void k_ln(
    const float* __restrict__ gamma, const float* __restrict__ beta,
    float* __restrict__ out)
{
    const int b   = blockIdx.x;
    const int tid = threadIdx.x;
    __shared__ float red[256];
    const float v = g_scores[(size_t)b * CC + tid];

    red[tid] = v; __syncthreads();
    for (int st = 128; st > 0; st >>= 1) {
        if (tid < st) red[tid] += red[tid + st];
        __syncthreads();
    }
    const float mu = red[0] * (1.f / CC); __syncthreads();
    const float d = v - mu;
    red[tid] = d * d; __syncthreads();
    for (int st = 128; st > 0; st >>= 1) {
        if (tid < st) red[tid] += red[tid + st];
        __syncthreads();
    }
    const float var = red[0] * (1.f / CC);
    out[(size_t)b * CC + tid] = d * rsqrtf(var + LN_EPS) * gamma[tid] + beta[tid];
}

// ---------------------------------------------------------------------------
extern "C" void kernel_launch(void* const* d_in, const int* in_sizes, int n_in,
                              void* d_out, int out_size)
{
    const float* x     = (const float*)d_in[0];
    const float* W1    = (const float*)d_in[1];
    const float* b1    = (const float*)d_in[2];
    const float* w2    = (const float*)d_in[3];
    const float* Wo    = (const float*)d_in[4];
    const float* bo    = (const float*)d_in[5];
    const float* gamma = (const float*)d_in[6];
    const float* beta  = (const float*)d_in[7];

    float* out = (float*)d_out;           // (B, C)
    float* wts = out + BB * CC;           // (B, H, T)

    cudaFuncSetAttribute(k_scores_mma, cudaFuncAttributeMaxDynamicSharedMemorySize,
                         SMEM_SC_TOTAL);

    k_prepw     <<<32, 256>>>(W1);
    k_scores_mma<<<dim3(TT / 128, BB), 256, SMEM_SC_TOTAL>>>(x, b1, w2);
    k_stats     <<<BB * HH, 256>>>();
    k_ctx       <<<dim3(NSPLIT, BB), 256>>>(x, wts);
    k_proj      <<<dim3(8, BB), 256>>>(Wo, bo);
    k_ln        <<<BB, 256>>>(gamma, beta, out);
}